// round 1
// baseline (speedup 1.0000x reference)
#include <cuda_runtime.h>

// Inverse 2D Haar wavelet (fused conv_transpose chain).
// x:   [8, 256, 128, 128] fp32, subbands LL | HL | LH | HH each 64 channels
// out: [8,  64, 256, 256] fp32
//
// out[2h,2w]     = 0.5*(LL+LH+HL+HH)
// out[2h,2w+1]   = 0.5*(LL-LH+HL-HH)
// out[2h+1,2w]   = 0.5*(LL+LH-HL-HH)
// out[2h+1,2w+1] = 0.5*(LL-LH-HL+HH)

#define B_  8
#define C_  64
#define H_  128
#define W_  128
#define W4_ (W_ / 4)               // 32 float4 per row
#define IN_PLANE   (H_ * W_)       // 16384
#define IN_BSTRIDE (4 * C_ * IN_PLANE)
#define OUT_W      (2 * W_)        // 256
#define OUT_PLANE  (4 * IN_PLANE)  // 65536
#define OUT_BSTRIDE (C_ * OUT_PLANE)

__global__ __launch_bounds__(256) void iwt_kernel(const float* __restrict__ x,
                                                  float* __restrict__ out) {
    int idx = blockIdx.x * blockDim.x + threadIdx.x;
    // idx -> (b, c, h, w4)
    int w4 = idx & (W4_ - 1);
    int t  = idx >> 5;             // / 32
    int h  = t & (H_ - 1);
    t >>= 7;                       // / 128
    int c  = t & (C_ - 1);
    int b  = t >> 6;               // / 64

    const float* base = x + (long long)b * IN_BSTRIDE + (long long)c * IN_PLANE
                          + h * W_ + (w4 << 2);

    float4 ll = *(const float4*)(base);
    float4 hl = *(const float4*)(base + 64  * IN_PLANE);
    float4 lh = *(const float4*)(base + 128 * IN_PLANE);
    float4 hh = *(const float4*)(base + 192 * IN_PLANE);

    float* obase = out + (long long)b * OUT_BSTRIDE + (long long)c * OUT_PLANE
                       + (2 * h) * OUT_W + (w4 << 3);

    float4 r0a, r0b, r1a, r1b;

    // element 0
    {
        float a = ll.x, bq = lh.x, cq = hl.x, d = hh.x;
        r0a.x = 0.5f * (a + bq + cq + d);
        r0a.y = 0.5f * (a - bq + cq - d);
        r1a.x = 0.5f * (a + bq - cq - d);
        r1a.y = 0.5f * (a - bq - cq + d);
    }
    // element 1
    {
        float a = ll.y, bq = lh.y, cq = hl.y, d = hh.y;
        r0a.z = 0.5f * (a + bq + cq + d);
        r0a.w = 0.5f * (a - bq + cq - d);
        r1a.z = 0.5f * (a + bq - cq - d);
        r1a.w = 0.5f * (a - bq - cq + d);
    }
    // element 2
    {
        float a = ll.z, bq = lh.z, cq = hl.z, d = hh.z;
        r0b.x = 0.5f * (a + bq + cq + d);
        r0b.y = 0.5f * (a - bq + cq - d);
        r1b.x = 0.5f * (a + bq - cq - d);
        r1b.y = 0.5f * (a - bq - cq + d);
    }
    // element 3
    {
        float a = ll.w, bq = lh.w, cq = hl.w, d = hh.w;
        r0b.z = 0.5f * (a + bq + cq + d);
        r0b.w = 0.5f * (a - bq + cq - d);
        r1b.z = 0.5f * (a + bq - cq - d);
        r1b.w = 0.5f * (a - bq - cq + d);
    }

    *(float4*)(obase)             = r0a;
    *(float4*)(obase + 4)         = r0b;
    *(float4*)(obase + OUT_W)     = r1a;
    *(float4*)(obase + OUT_W + 4) = r1b;
}

extern "C" void kernel_launch(void* const* d_in, const int* in_sizes, int n_in,
                              void* d_out, int out_size) {
    const float* x = (const float*)d_in[0];
    float* out = (float*)d_out;
    const int total4 = B_ * C_ * H_ * W4_;   // 2,097,152 threads
    iwt_kernel<<<total4 / 256, 256>>>(x, out);
}

// round 2
// speedup vs baseline: 1.0921x; 1.0921x over previous
#include <cuda_runtime.h>

// Inverse 2D Haar wavelet (fused conv_transpose chain).
// x:   [8, 256, 128, 128] fp32, subbands LL | HL | LH | HH each 64 channels
// out: [8,  64, 256, 256] fp32
//
// out[2h,2w]     = 0.5*(LL+LH+HL+HH)
// out[2h,2w+1]   = 0.5*(LL-LH+HL-HH)
// out[2h+1,2w]   = 0.5*(LL+LH-HL-HH)
// out[2h+1,2w+1] = 0.5*(LL-LH-HL+HH)
//
// Each thread: one float2 of input per subband -> one float4 per output row.
// Every load (LDG.64) and store (STG.128) is fully contiguous across the warp.

#define B_  8
#define C_  64
#define H_  128
#define W_  128
#define W2_ (W_ / 2)               // 64 float2 per row
#define IN_PLANE   (H_ * W_)       // 16384
#define IN_BSTRIDE (4 * C_ * IN_PLANE)
#define OUT_W      (2 * W_)        // 256
#define OUT_PLANE  (4 * IN_PLANE)  // 65536
#define OUT_BSTRIDE (C_ * OUT_PLANE)

__global__ __launch_bounds__(256) void iwt_kernel(const float* __restrict__ x,
                                                  float* __restrict__ out) {
    int idx = blockIdx.x * blockDim.x + threadIdx.x;
    // idx -> (b, c, h, w2)
    int w2 = idx & (W2_ - 1);
    int t  = idx >> 6;             // / 64
    int h  = t & (H_ - 1);
    t >>= 7;                       // / 128
    int c  = t & (C_ - 1);
    int b  = t >> 6;               // / 64

    const float* base = x + (long long)b * IN_BSTRIDE + (long long)c * IN_PLANE
                          + h * W_ + (w2 << 1);

    float2 ll = *(const float2*)(base);
    float2 hl = *(const float2*)(base + 64  * IN_PLANE);
    float2 lh = *(const float2*)(base + 128 * IN_PLANE);
    float2 hh = *(const float2*)(base + 192 * IN_PLANE);

    float* obase = out + (long long)b * OUT_BSTRIDE + (long long)c * OUT_PLANE
                       + (2 * h) * OUT_W + (w2 << 2);

    float4 r0, r1;

    // element 0 -> out columns 0,1
    {
        float a = ll.x, bq = lh.x, cq = hl.x, d = hh.x;
        float apb = a + bq, amb = a - bq, cpd = cq + d, cmd = cq - d;
        r0.x = 0.5f * (apb + cpd);
        r0.y = 0.5f * (amb + cmd);
        r1.x = 0.5f * (apb - cpd);
        r1.y = 0.5f * (amb - cmd);
    }
    // element 1 -> out columns 2,3
    {
        float a = ll.y, bq = lh.y, cq = hl.y, d = hh.y;
        float apb = a + bq, amb = a - bq, cpd = cq + d, cmd = cq - d;
        r0.z = 0.5f * (apb + cpd);
        r0.w = 0.5f * (amb + cmd);
        r1.z = 0.5f * (apb - cpd);
        r1.w = 0.5f * (amb - cmd);
    }

    *(float4*)(obase)         = r0;
    *(float4*)(obase + OUT_W) = r1;
}

extern "C" void kernel_launch(void* const* d_in, const int* in_sizes, int n_in,
                              void* d_out, int out_size) {
    const float* x = (const float*)d_in[0];
    float* out = (float*)d_out;
    const int total = B_ * C_ * H_ * W2_;   // 4,194,304 threads
    iwt_kernel<<<total / 256, 256>>>(x, out);
}